// round 3
// baseline (speedup 1.0000x reference)
#include <cuda_runtime.h>
#include <math.h>

// Problem constants
#define NC   64
#define NG   8
#define GS   32
#define IN_CH 2048
#define OUT_CH 256
#define NP   5
#define ROWS (NC*NG*GS)      // 16384
#define GN   (NG*GS)         // 256 rows per class
#define INV_SQRT_O 0.0625f   // 1/sqrt(256)

// ---------------- scratch (device globals; no allocation allowed) ----------------
__device__ float g_e    [(size_t)ROWS * OUT_CH];     // e / per-row inner embeddings
__device__ float g_ctx  [(size_t)ROWS * IN_CH];      // att @ X
__device__ float g_feats[(size_t)ROWS * IN_CH];      // X + relu(ctx @ T^T)
__device__ float g_fae  [(size_t)ROWS * OUT_CH];     // feats @ inter_w1^T
__device__ float g_pe   [(size_t)NC * NP * OUT_CH];  // protos @ inter_w2^T
__device__ float g_att2 [(size_t)NC * NP * GN];      // inter attention weights

// ---------------------------------------------------------------------------------
// SGEMM: C[M,N] = A[M,K] * B[N,K]^T   (both row-major, K contiguous -> "NT")
// BM=BN=128, BK=16, 256 threads, 8x8 microtile.
// epi==1: C = X + relu(acc)   (X indexed same as C)
// M may be non-multiple of 128 (loads clamped, stores guarded). N,K multiples of 16/128.
// ---------------------------------------------------------------------------------
#define SST 132   // smem row stride (padded, float4-aligned)

__global__ void __launch_bounds__(256)
sgemm_nt(const float* __restrict__ A, const float* __restrict__ B,
         float* __restrict__ C, const float* __restrict__ X,
         int M, int N, int K, int epi)
{
    __shared__ float As[16 * SST];
    __shared__ float Bs[16 * SST];

    const int tid = threadIdx.x;
    const int tx  = tid & 15;       // n dir
    const int ty  = tid >> 4;       // m dir
    const int bm  = blockIdx.y * 128;
    const int bn  = blockIdx.x * 128;

    const int lrow = tid >> 2;          // 0..63
    const int lcol = (tid & 3) << 2;    // 0,4,8,12

    float acc[8][8];
#pragma unroll
    for (int i = 0; i < 8; i++)
#pragma unroll
        for (int j = 0; j < 8; j++) acc[i][j] = 0.f;

    for (int k0 = 0; k0 < K; k0 += 16) {
#pragma unroll
        for (int r = 0; r < 2; r++) {
            int row = lrow + r * 64;
            int gr  = bm + row; if (gr > M - 1) gr = M - 1;
            float4 va = *(const float4*)(A + (size_t)gr * K + k0 + lcol);
            As[(lcol + 0) * SST + row] = va.x;
            As[(lcol + 1) * SST + row] = va.y;
            As[(lcol + 2) * SST + row] = va.z;
            As[(lcol + 3) * SST + row] = va.w;
            float4 vb = *(const float4*)(B + (size_t)(bn + row) * K + k0 + lcol);
            Bs[(lcol + 0) * SST + row] = vb.x;
            Bs[(lcol + 1) * SST + row] = vb.y;
            Bs[(lcol + 2) * SST + row] = vb.z;
            Bs[(lcol + 3) * SST + row] = vb.w;
        }
        __syncthreads();
#pragma unroll
        for (int kk = 0; kk < 16; kk++) {
            float a[8], b[8];
            *(float4*)(a)     = *(const float4*)&As[kk * SST + ty * 4];
            *(float4*)(a + 4) = *(const float4*)&As[kk * SST + 64 + ty * 4];
            *(float4*)(b)     = *(const float4*)&Bs[kk * SST + tx * 4];
            *(float4*)(b + 4) = *(const float4*)&Bs[kk * SST + 64 + tx * 4];
#pragma unroll
            for (int i = 0; i < 8; i++)
#pragma unroll
                for (int j = 0; j < 8; j++)
                    acc[i][j] += a[i] * b[j];
        }
        __syncthreads();
    }

#pragma unroll
    for (int i = 0; i < 8; i++) {
        int gm = bm + ((i < 4) ? (ty * 4 + i) : (64 + ty * 4 + i - 4));
        if (gm >= M) continue;
#pragma unroll
        for (int j = 0; j < 8; j++) {
            int gn = bn + ((j < 4) ? (tx * 4 + j) : (64 + tx * 4 + j - 4));
            float v = acc[i][j];
            if (epi) v = X[(size_t)gm * N + gn] + fmaxf(v, 0.f);
            C[(size_t)gm * N + gn] = v;
        }
    }
}

// ---------------------------------------------------------------------------------
// Inner attention, fused: per (c,g) block b (512 blocks, 256 threads)
//   S[n,m] = dot(e[n], e[m]) / 16 ; att = softmax_m(S) ; ctx = att @ X_block
// ---------------------------------------------------------------------------------
#define EST 257
__global__ void __launch_bounds__(256)
inner_attn_kernel(const float* __restrict__ e, const float* __restrict__ X,
                  float* __restrict__ ctx)
{
    const int b   = blockIdx.x;           // c*8+g
    const int tid = threadIdx.x;
    __shared__ float se[GS * EST];
    __shared__ float satt[GS * 33];

    const float* eb = e + (size_t)b * GS * OUT_CH;
    for (int i = tid; i < GS * OUT_CH; i += 256)
        se[(i >> 8) * EST + (i & 255)] = eb[i];
    __syncthreads();

    {   // 4 score entries per thread
        const int n  = tid >> 3;
        const int m0 = (tid & 7) << 2;
        const float* en  = &se[n * EST];
        const float* em0 = &se[(m0 + 0) * EST];
        const float* em1 = &se[(m0 + 1) * EST];
        const float* em2 = &se[(m0 + 2) * EST];
        const float* em3 = &se[(m0 + 3) * EST];
        float s0 = 0.f, s1 = 0.f, s2 = 0.f, s3 = 0.f;
#pragma unroll 8
        for (int k = 0; k < OUT_CH; k++) {
            float a = en[k];
            s0 += a * em0[k];
            s1 += a * em1[k];
            s2 += a * em2[k];
            s3 += a * em3[k];
        }
        satt[n * 33 + m0 + 0] = s0 * INV_SQRT_O;
        satt[n * 33 + m0 + 1] = s1 * INV_SQRT_O;
        satt[n * 33 + m0 + 2] = s2 * INV_SQRT_O;
        satt[n * 33 + m0 + 3] = s3 * INV_SQRT_O;
    }
    __syncthreads();

    if (tid < GS) {   // row softmax (tiny)
        float mx = -1e30f;
#pragma unroll
        for (int m = 0; m < GS; m++) mx = fmaxf(mx, satt[tid * 33 + m]);
        float sum = 0.f;
#pragma unroll
        for (int m = 0; m < GS; m++) {
            float v = expf(satt[tid * 33 + m] - mx);
            satt[tid * 33 + m] = v;
            sum += v;
        }
        float inv = 1.f / sum;
#pragma unroll
        for (int m = 0; m < GS; m++) satt[tid * 33 + m] *= inv;
    }
    __syncthreads();

    const float* xb = X   + (size_t)b * GS * IN_CH;
    float*       cb = ctx + (size_t)b * GS * IN_CH;
    for (int d = tid; d < IN_CH; d += 256) {
        float acc[GS];
#pragma unroll
        for (int n = 0; n < GS; n++) acc[n] = 0.f;
#pragma unroll 4
        for (int m = 0; m < GS; m++) {
            float xv = xb[(size_t)m * IN_CH + d];
#pragma unroll
            for (int n = 0; n < GS; n++) acc[n] += satt[n * 33 + m] * xv;
        }
#pragma unroll
        for (int n = 0; n < GS; n++) cb[(size_t)n * IN_CH + d] = acc[n];
    }
}

// ---------------------------------------------------------------------------------
// Inter attention logits + softmax: per class c (64 blocks, 256 threads)
//   L[p,n] = dot(p_e[c,p], fa_e[c,n]) / 16 ; att2[p,:] = softmax_n(L[p,:])
// ---------------------------------------------------------------------------------
__global__ void __launch_bounds__(256)
inter_attn_kernel(const float* __restrict__ pe, const float* __restrict__ fae,
                  float* __restrict__ att2)
{
    const int c    = blockIdx.x;
    const int tid  = threadIdx.x;
    const int lane = tid & 31;
    const int w    = tid >> 5;     // 8 warps
    __shared__ float spe[NP * OUT_CH];
    __shared__ float sl [NP * GN];

    for (int i = tid; i < NP * OUT_CH; i += 256)
        spe[i] = pe[(size_t)c * NP * OUT_CH + i];
    __syncthreads();

    for (int n = w; n < GN; n += 8) {
        const float* fr = fae + ((size_t)c * GN + n) * OUT_CH;
        float acc[NP] = {0.f, 0.f, 0.f, 0.f, 0.f};
        for (int k = lane; k < OUT_CH; k += 32) {
            float f = fr[k];
#pragma unroll
            for (int p = 0; p < NP; p++) acc[p] += spe[p * OUT_CH + k] * f;
        }
#pragma unroll
        for (int p = 0; p < NP; p++) {
#pragma unroll
            for (int off = 16; off; off >>= 1)
                acc[p] += __shfl_xor_sync(0xffffffffu, acc[p], off);
            if (lane == 0) sl[p * GN + n] = acc[p] * INV_SQRT_O;
        }
    }
    __syncthreads();

    if (w < NP) {   // softmax over n, one warp per p
        float mx = -1e30f;
        for (int n = lane; n < GN; n += 32) mx = fmaxf(mx, sl[w * GN + n]);
#pragma unroll
        for (int off = 16; off; off >>= 1)
            mx = fmaxf(mx, __shfl_xor_sync(0xffffffffu, mx, off));
        float sum = 0.f;
        for (int n = lane; n < GN; n += 32) {
            float v = expf(sl[w * GN + n] - mx);
            sl[w * GN + n] = v;
            sum += v;
        }
#pragma unroll
        for (int off = 16; off; off >>= 1)
            sum += __shfl_xor_sync(0xffffffffu, sum, off);
        float inv = 1.f / sum;
        for (int n = lane; n < GN; n += 32)
            att2[(size_t)c * NP * GN + w * GN + n] = sl[w * GN + n] * inv;
    }
}

// ---------------------------------------------------------------------------------
// Output gather: out[c,p,d] = sum_n att2[c,p,n] * feats[c,n,d]
// grid (64, IN_CH/256), 256 threads; memory-bound.
// ---------------------------------------------------------------------------------
__global__ void __launch_bounds__(256)
out_kernel(const float* __restrict__ att2, const float* __restrict__ feats,
           float* __restrict__ out)
{
    const int c = blockIdx.x;
    const int d = blockIdx.y * 256 + threadIdx.x;
    __shared__ float sa[NP * GN];
    for (int i = threadIdx.x; i < NP * GN; i += 256)
        sa[i] = att2[(size_t)c * NP * GN + i];
    __syncthreads();

    const float* fb = feats + (size_t)c * GN * IN_CH + d;
    float acc[NP] = {0.f, 0.f, 0.f, 0.f, 0.f};
#pragma unroll 4
    for (int n = 0; n < GN; n++) {
        float f = fb[(size_t)n * IN_CH];
#pragma unroll
        for (int p = 0; p < NP; p++) acc[p] += sa[p * GN + n] * f;
    }
#pragma unroll
    for (int p = 0; p < NP; p++)
        out[((size_t)c * NP + p) * IN_CH + d] = acc[p];
}

// ---------------------------------------------------------------------------------
extern "C" void kernel_launch(void* const* d_in, const int* in_sizes, int n_in,
                              void* d_out, int out_size)
{
    const float* topk   = (const float*)d_in[0];  // [64,8,32,2048]
    const float* protos = (const float*)d_in[1];  // [64,5,2048]
    const float* w1     = (const float*)d_in[2];  // [256,2048]
    const float* trans  = (const float*)d_in[3];  // [2048,2048]
    const float* iw1    = (const float*)d_in[4];  // [256,2048]
    const float* iw2    = (const float*)d_in[5];  // [256,2048]
    float* out = (float*)d_out;

    float *e, *ctx, *feats, *fae, *pe, *att2;
    cudaGetSymbolAddress((void**)&e,     g_e);
    cudaGetSymbolAddress((void**)&ctx,   g_ctx);
    cudaGetSymbolAddress((void**)&feats, g_feats);
    cudaGetSymbolAddress((void**)&fae,   g_fae);
    cudaGetSymbolAddress((void**)&pe,    g_pe);
    cudaGetSymbolAddress((void**)&att2,  g_att2);

    // 1) e = X @ inner_w1^T                [16384,256]
    sgemm_nt<<<dim3(OUT_CH / 128, ROWS / 128), 256>>>(topk, w1, e, nullptr,
                                                      ROWS, OUT_CH, IN_CH, 0);
    // 2) inner attention (S, softmax, ctx) fused, one CTA per (c,g)
    inner_attn_kernel<<<NC * NG, 256>>>(e, topk, ctx);
    // 3) feats = X + relu(ctx @ trans^T)   [16384,2048]  (dominant GEMM)
    sgemm_nt<<<dim3(IN_CH / 128, ROWS / 128), 256>>>(ctx, trans, feats, topk,
                                                     ROWS, IN_CH, IN_CH, 1);
    // 4) fa_e = feats @ inter_w1^T         [16384,256]
    sgemm_nt<<<dim3(OUT_CH / 128, ROWS / 128), 256>>>(feats, iw1, fae, nullptr,
                                                      ROWS, OUT_CH, IN_CH, 0);
    // 5) p_e = protos @ inter_w2^T         [320,256]  (M=320 -> guarded tiles)
    sgemm_nt<<<dim3(OUT_CH / 128, (NC * NP + 127) / 128), 256>>>(protos, iw2, pe, nullptr,
                                                                 NC * NP, OUT_CH, IN_CH, 0);
    // 6) inter attention logits + softmax, one CTA per class
    inter_attn_kernel<<<NC, 256>>>(pe, fae, att2);
    // 7) out = att2 @ feats_all            [64,5,2048]
    out_kernel<<<dim3(NC, IN_CH / 256), 256>>>(att2, feats, out);
}

// round 11
// speedup vs baseline: 2.1675x; 2.1675x over previous
#include <cuda_runtime.h>
#include <cstdint>
#include <math.h>

// Problem constants
#define NC   64
#define NG   8
#define GS   32
#define IN_CH 2048
#define OUT_CH 256
#define NP   5
#define ROWS (NC*NG*GS)      // 16384
#define GN   (NG*GS)         // 256 rows per class
#define INV_SQRT_O 0.0625f   // 1/sqrt(256)

// ---------------- scratch (device globals; no allocation allowed) ----------------
__device__ float g_e    [(size_t)ROWS * OUT_CH];
__device__ float g_ctx  [(size_t)ROWS * IN_CH];
__device__ float g_feats[(size_t)ROWS * IN_CH];
__device__ float g_fae  [(size_t)ROWS * OUT_CH];
__device__ float g_pe   [(size_t)NC * NP * OUT_CH];
__device__ float g_att2 [(size_t)NC * NP * GN];

// ======================= helpers (family-portable PTX only) ======================
__device__ __forceinline__ uint32_t smem_u32(const void* p) {
    uint32_t a;
    asm("{ .reg .u64 t; cvta.to.shared.u64 t, %1; cvt.u32.u64 %0, t; }" : "=r"(a) : "l"(p));
    return a;
}
__device__ __forceinline__ uint32_t f2tf32(float x) {
    uint32_t y;
    asm("cvt.rna.tf32.f32 %0, %1;" : "=r"(y) : "f"(x));
    return y;
}
#define CP_ASYNC16(dst, src) \
    asm volatile("cp.async.cg.shared.global [%0], [%1], 16;" :: "r"(dst), "l"(src) : "memory")
#define CP_COMMIT()  asm volatile("cp.async.commit_group;" ::: "memory")
#define CP_WAIT1()   asm volatile("cp.async.wait_group 1;" ::: "memory")

__device__ __forceinline__ void mma_tf32(float* c, const uint32_t* a, const uint32_t* b) {
    asm volatile(
        "mma.sync.aligned.m16n8k8.row.col.f32.tf32.tf32.f32 "
        "{%0,%1,%2,%3}, {%4,%5,%6,%7}, {%8,%9}, {%0,%1,%2,%3};"
        : "+f"(c[0]), "+f"(c[1]), "+f"(c[2]), "+f"(c[3])
        : "r"(a[0]), "r"(a[1]), "r"(a[2]), "r"(a[3]), "r"(b[0]), "r"(b[1]));
}

// ---------------------------------------------------------------------------------
// tf32 mma.sync GEMM: C[M,N] = A[M,K] * B[N,K]^T  (both row-major, K contiguous)
// BM=BN=128, BK=16, 256 threads (8 warps 4m x 2n, warp tile 32x64), 3-stage cp.async.
// epi==1: C = X + relu(acc). N multiple of 128, K multiple of 16, M guarded.
// smem per stage: A 128x20 floats (10240B) + B same -> 20480B; 3 stages = 61440B.
// ---------------------------------------------------------------------------------
#define SROW   20
#define STG_F  (2 * 128 * SROW)          // floats per stage (A+B)
#define SM_GEMM_BYTES (3 * STG_F * 4)    // 61440

__global__ void __launch_bounds__(256)
mgemm_tf32(const float* __restrict__ A, const float* __restrict__ B,
           float* __restrict__ C, const float* __restrict__ X,
           int M, int N, int K, int epi)
{
    extern __shared__ float sm[];
    const int tid  = threadIdx.x;
    const int wid  = tid >> 5;
    const int lane = tid & 31;
    const int g    = lane >> 2;          // 0..7
    const int tig  = lane & 3;           // 0..3
    const int wm   = wid & 3;            // warp m index (0..3)
    const int wn   = wid >> 2;           // warp n index (0..1)
    const int bm   = blockIdx.y * 128;
    const int bn   = blockIdx.x * 128;
    const int KT   = K >> 4;             // 16-wide K chunks

    // ---- global load setup: each thread copies 2x16B of A and 2x16B of B per stage
    const int lr = tid >> 2;             // 0..63
    const int lc = (tid & 3) << 2;       // 0,4,8,12
    int gr0 = bm + lr;      if (gr0 > M - 1) gr0 = M - 1;
    int gr1 = bm + lr + 64; if (gr1 > M - 1) gr1 = M - 1;
    const float* a0p = A + (size_t)gr0 * K + lc;
    const float* a1p = A + (size_t)gr1 * K + lc;
    const float* b0p = B + (size_t)(bn + lr)      * K + lc;
    const float* b1p = B + (size_t)(bn + lr + 64) * K + lc;

    const uint32_t sbase = smem_u32(sm);
    const uint32_t doffA0 = (uint32_t)((lr      * SROW + lc) * 4);
    const uint32_t doffA1 = (uint32_t)(((lr+64) * SROW + lc) * 4);
    const uint32_t stgB   = 128 * SROW * 4;  // byte offset of B within a stage

    float acc[2][8][4];
#pragma unroll
    for (int mt = 0; mt < 2; mt++)
#pragma unroll
        for (int nt = 0; nt < 8; nt++)
#pragma unroll
            for (int q = 0; q < 4; q++) acc[mt][nt][q] = 0.f;

    // ---- prologue: issue stages 0 and 1
#pragma unroll
    for (int p = 0; p < 2; p++) {
        const uint32_t sb = sbase + p * (STG_F * 4);
        const int k0 = p * 16;
        CP_ASYNC16(sb + doffA0,        a0p + k0);
        CP_ASYNC16(sb + doffA1,        a1p + k0);
        CP_ASYNC16(sb + stgB + doffA0, b0p + k0);
        CP_ASYNC16(sb + stgB + doffA1, b1p + k0);
        CP_COMMIT();
    }

    for (int it = 0; it < KT; ++it) {
        CP_WAIT1();
        __syncthreads();

        const int s = it % 3;
        const float* As = sm + s * STG_F;
        const float* Bs = As + 128 * SROW;

#pragma unroll
        for (int kk = 0; kk < 16; kk += 8) {
            uint32_t af[2][4];
#pragma unroll
            for (int mt = 0; mt < 2; mt++) {
                const int m = wm * 32 + mt * 16;
                af[mt][0] = f2tf32(As[(m + g    ) * SROW + kk + tig    ]);
                af[mt][1] = f2tf32(As[(m + g + 8) * SROW + kk + tig    ]);
                af[mt][2] = f2tf32(As[(m + g    ) * SROW + kk + tig + 4]);
                af[mt][3] = f2tf32(As[(m + g + 8) * SROW + kk + tig + 4]);
            }
            uint32_t bf[8][2];
#pragma unroll
            for (int nt = 0; nt < 8; nt++) {
                const int n = wn * 64 + nt * 8;
                bf[nt][0] = f2tf32(Bs[(n + g) * SROW + kk + tig    ]);
                bf[nt][1] = f2tf32(Bs[(n + g) * SROW + kk + tig + 4]);
            }
#pragma unroll
            for (int mt = 0; mt < 2; mt++)
#pragma unroll
                for (int nt = 0; nt < 8; nt++)
                    mma_tf32(acc[mt][nt], af[mt], bf[nt]);
        }

        __syncthreads();
        if (it + 2 < KT) {
            const int ps = (it + 2) % 3;
            const uint32_t sb = sbase + ps * (STG_F * 4);
            const int k0 = (it + 2) * 16;
            CP_ASYNC16(sb + doffA0,        a0p + k0);
            CP_ASYNC16(sb + doffA1,        a1p + k0);
            CP_ASYNC16(sb + stgB + doffA0, b0p + k0);
            CP_ASYNC16(sb + stgB + doffA1, b1p + k0);
        }
        CP_COMMIT();
    }

    // ---- epilogue
#pragma unroll
    for (int mt = 0; mt < 2; mt++) {
        const int r0 = bm + wm * 32 + mt * 16 + g;
        const int r1 = r0 + 8;
#pragma unroll
        for (int nt = 0; nt < 8; nt++) {
            const int col = bn + wn * 64 + nt * 8 + 2 * tig;
            if (r0 < M) {
                float v0 = acc[mt][nt][0], v1 = acc[mt][nt][1];
                if (epi) {
                    const float2 x = *(const float2*)(X + (size_t)r0 * N + col);
                    v0 = x.x + fmaxf(v0, 0.f);
                    v1 = x.y + fmaxf(v1, 0.f);
                }
                *(float2*)(C + (size_t)r0 * N + col) = make_float2(v0, v1);
            }
            if (r1 < M) {
                float v2 = acc[mt][nt][2], v3 = acc[mt][nt][3];
                if (epi) {
                    const float2 x = *(const float2*)(X + (size_t)r1 * N + col);
                    v2 = x.x + fmaxf(v2, 0.f);
                    v3 = x.y + fmaxf(v3, 0.f);
                }
                *(float2*)(C + (size_t)r1 * N + col) = make_float2(v2, v3);
            }
        }
    }
}

// ---------------------------------------------------------------------------------
// Inner attention, fused: per (c,g) block b (512 blocks, 256 threads)
// ---------------------------------------------------------------------------------
#define EST 257
__global__ void __launch_bounds__(256)
inner_attn_kernel(const float* __restrict__ e, const float* __restrict__ X,
                  float* __restrict__ ctx)
{
    const int b   = blockIdx.x;
    const int tid = threadIdx.x;
    __shared__ float se[GS * EST];
    __shared__ float satt[GS * 33];

    const float* eb = e + (size_t)b * GS * OUT_CH;
    for (int i = tid; i < GS * OUT_CH; i += 256)
        se[(i >> 8) * EST + (i & 255)] = eb[i];
    __syncthreads();

    {
        const int n  = tid >> 3;
        const int m0 = (tid & 7) << 2;
        const float* en  = &se[n * EST];
        const float* em0 = &se[(m0 + 0) * EST];
        const float* em1 = &se[(m0 + 1) * EST];
        const float* em2 = &se[(m0 + 2) * EST];
        const float* em3 = &se[(m0 + 3) * EST];
        float s0 = 0.f, s1 = 0.f, s2 = 0.f, s3 = 0.f;
#pragma unroll 8
        for (int k = 0; k < OUT_CH; k++) {
            float a = en[k];
            s0 += a * em0[k]; s1 += a * em1[k]; s2 += a * em2[k]; s3 += a * em3[k];
        }
        satt[n * 33 + m0 + 0] = s0 * INV_SQRT_O;
        satt[n * 33 + m0 + 1] = s1 * INV_SQRT_O;
        satt[n * 33 + m0 + 2] = s2 * INV_SQRT_O;
        satt[n * 33 + m0 + 3] = s3 * INV_SQRT_O;
    }
    __syncthreads();

    if (tid < GS) {
        float mx = -1e30f;
#pragma unroll
        for (int m = 0; m < GS; m++) mx = fmaxf(mx, satt[tid * 33 + m]);
        float sum = 0.f;
#pragma unroll
        for (int m = 0; m < GS; m++) {
            float v = expf(satt[tid * 33 + m] - mx);
            satt[tid * 33 + m] = v; sum += v;
        }
        float inv = 1.f / sum;
#pragma unroll
        for (int m = 0; m < GS; m++) satt[tid * 33 + m] *= inv;
    }
    __syncthreads();

    const float* xb = X   + (size_t)b * GS * IN_CH;
    float*       cb = ctx + (size_t)b * GS * IN_CH;
    for (int d = tid; d < IN_CH; d += 256) {
        float acc[GS];
#pragma unroll
        for (int n = 0; n < GS; n++) acc[n] = 0.f;
#pragma unroll 4
        for (int m = 0; m < GS; m++) {
            float xv = xb[(size_t)m * IN_CH + d];
#pragma unroll
            for (int n = 0; n < GS; n++) acc[n] += satt[n * 33 + m] * xv;
        }
#pragma unroll
        for (int n = 0; n < GS; n++) cb[(size_t)n * IN_CH + d] = acc[n];
    }
}

// ---------------------------------------------------------------------------------
// Inter attention logits + softmax: per class c
// ---------------------------------------------------------------------------------
__global__ void __launch_bounds__(256)
inter_attn_kernel(const float* __restrict__ pe, const float* __restrict__ fae,
                  float* __restrict__ att2)
{
    const int c    = blockIdx.x;
    const int tid  = threadIdx.x;
    const int lane = tid & 31;
    const int w    = tid >> 5;
    __shared__ float spe[NP * OUT_CH];
    __shared__ float sl [NP * GN];

    for (int i = tid; i < NP * OUT_CH; i += 256)
        spe[i] = pe[(size_t)c * NP * OUT_CH + i];
    __syncthreads();

    for (int n = w; n < GN; n += 8) {
        const float* fr = fae + ((size_t)c * GN + n) * OUT_CH;
        float acc[NP] = {0.f, 0.f, 0.f, 0.f, 0.f};
        for (int k = lane; k < OUT_CH; k += 32) {
            float f = fr[k];
#pragma unroll
            for (int p = 0; p < NP; p++) acc[p] += spe[p * OUT_CH + k] * f;
        }
#pragma unroll
        for (int p = 0; p < NP; p++) {
#pragma unroll
            for (int off = 16; off; off >>= 1)
                acc[p] += __shfl_xor_sync(0xffffffffu, acc[p], off);
            if (lane == 0) sl[p * GN + n] = acc[p] * INV_SQRT_O;
        }
    }
    __syncthreads();

    if (w < NP) {
        float mx = -1e30f;
        for (int n = lane; n < GN; n += 32) mx = fmaxf(mx, sl[w * GN + n]);
#pragma unroll
        for (int off = 16; off; off >>= 1)
            mx = fmaxf(mx, __shfl_xor_sync(0xffffffffu, mx, off));
        float sum = 0.f;
        for (int n = lane; n < GN; n += 32) {
            float v = expf(sl[w * GN + n] - mx);
            sl[w * GN + n] = v; sum += v;
        }
#pragma unroll
        for (int off = 16; off; off >>= 1)
            sum += __shfl_xor_sync(0xffffffffu, sum, off);
        float inv = 1.f / sum;
        for (int n = lane; n < GN; n += 32)
            att2[(size_t)c * NP * GN + w * GN + n] = sl[w * GN + n] * inv;
    }
}

// ---------------------------------------------------------------------------------
// Output gather: out[c,p,d] = sum_n att2[c,p,n] * feats[c,n,d]
// ---------------------------------------------------------------------------------
__global__ void __launch_bounds__(256)
out_kernel(const float* __restrict__ att2, const float* __restrict__ feats,
           float* __restrict__ out)
{
    const int c = blockIdx.x;
    const int d = blockIdx.y * 256 + threadIdx.x;
    __shared__ float sa[NP * GN];
    for (int i = threadIdx.x; i < NP * GN; i += 256)
        sa[i] = att2[(size_t)c * NP * GN + i];
    __syncthreads();

    const float* fb = feats + (size_t)c * GN * IN_CH + d;
    float acc[NP] = {0.f, 0.f, 0.f, 0.f, 0.f};
#pragma unroll 4
    for (int n = 0; n < GN; n++) {
        float f = fb[(size_t)n * IN_CH];
#pragma unroll
        for (int p = 0; p < NP; p++) acc[p] += sa[p * GN + n] * f;
    }
#pragma unroll
    for (int p = 0; p < NP; p++)
        out[((size_t)c * NP + p) * IN_CH + d] = acc[p];
}

// ---------------------------------------------------------------------------------
extern "C" void kernel_launch(void* const* d_in, const int* in_sizes, int n_in,
                              void* d_out, int out_size)
{
    const float* topk   = (const float*)d_in[0];  // [64,8,32,2048]
    const float* protos = (const float*)d_in[1];  // [64,5,2048]
    const float* w1     = (const float*)d_in[2];  // [256,2048]
    const float* trans  = (const float*)d_in[3];  // [2048,2048]
    const float* iw1    = (const float*)d_in[4];  // [256,2048]
    const float* iw2    = (const float*)d_in[5];  // [256,2048]
    float* out = (float*)d_out;

    float *e, *ctx, *feats, *fae, *pe, *att2;
    cudaGetSymbolAddress((void**)&e,     g_e);
    cudaGetSymbolAddress((void**)&ctx,   g_ctx);
    cudaGetSymbolAddress((void**)&feats, g_feats);
    cudaGetSymbolAddress((void**)&fae,   g_fae);
    cudaGetSymbolAddress((void**)&pe,    g_pe);
    cudaGetSymbolAddress((void**)&att2,  g_att2);

    cudaFuncSetAttribute(mgemm_tf32, cudaFuncAttributeMaxDynamicSharedMemorySize,
                         SM_GEMM_BYTES);

    // 1) e = X @ inner_w1^T                [16384,256]
    mgemm_tf32<<<dim3(OUT_CH / 128, ROWS / 128), 256, SM_GEMM_BYTES>>>(
        topk, w1, e, nullptr, ROWS, OUT_CH, IN_CH, 0);
    // 2) inner attention (S, softmax, ctx) fused
    inner_attn_kernel<<<NC * NG, 256>>>(e, topk, ctx);
    // 3) feats = X + relu(ctx @ trans^T)   [16384,2048]  (dominant GEMM)
    mgemm_tf32<<<dim3(IN_CH / 128, ROWS / 128), 256, SM_GEMM_BYTES>>>(
        ctx, trans, feats, topk, ROWS, IN_CH, IN_CH, 1);
    // 4) fa_e = feats @ inter_w1^T         [16384,256]
    mgemm_tf32<<<dim3(OUT_CH / 128, ROWS / 128), 256, SM_GEMM_BYTES>>>(
        feats, iw1, fae, nullptr, ROWS, OUT_CH, IN_CH, 0);
    // 5) p_e = protos @ inter_w2^T         [320,256]
    mgemm_tf32<<<dim3(OUT_CH / 128, (NC * NP + 127) / 128), 256, SM_GEMM_BYTES>>>(
        protos, iw2, pe, nullptr, NC * NP, OUT_CH, IN_CH, 0);
    // 6) inter attention logits + softmax
    inter_attn_kernel<<<NC, 256>>>(pe, fae, att2);
    // 7) out = att2 @ feats_all            [64,5,2048]
    out_kernel<<<dim3(NC, IN_CH / 256), 256>>>(att2, feats, out);
}